// round 15
// baseline (speedup 1.0000x reference)
#include <cuda_runtime.h>
#include <math.h>

#define BB 8
#define RR 4096
#define CC 1024
#define NROW (BB * RR)

// Scratch + sync state (no allocations allowed; zero-init at module load,
// self-reset every run for graph replay).
__device__ float    d_mags[NROW];
__device__ float    d_thr[BB];
__device__ unsigned d_cnt[BB];    // norms-blocks-done counter per batch
__device__ unsigned d_flag[BB];   // thr-ready flag per batch
__device__ unsigned d_ocnt[BB];   // out-blocks-done counter per batch (for reset)

// Group schedule: 16 groups of 512 blocks, interleaved so O(b) is scheduled
// ~2 groups after N(b) completes -> kept-row re-reads of batch b hit L2
// (intervening traffic ~40MB << 126MB L2) and read/write streams interleave
// across the whole kernel instead of serializing into two phases.
// phase: 0 = N (norms+threshold), 1 = O (output)
__constant__ signed char g_phase[16] = {0,0,1,0,1,0,1,0,1,0,1,0,1,0,1,1};
__constant__ signed char g_batch[16] = {0,1,0,2,1,3,2,4,3,5,4,6,5,7,6,7};

// Branch-free two-sum accumulate: s += t with running compensation c.
__device__ __forceinline__ void twosum_acc(float& s, float& c, float t) {
    float y  = s + t;
    float bp = y - s;
    c += (s - (y - bp)) + (t - bp);
    s = y;
}
__device__ __forceinline__ void twosum_merge(float& s, float& c, float so, float co) {
    float S  = s + so;
    float bp = S - s;
    float e  = (s - (S - bp)) + (so - bp);
    c = c + co + e;
    s = S;
}

// ---------------------------------------------------------------------------
// One launch, interleaved producer/consumer groups (see g_phase/g_batch):
//  N(b): per-row compensated-fp32 L2 norms of batch b (512 blocks). The last
//        block (atomic counter) computes k (fp64 score dot -> fp32 sigmoid ->
//        trunc, matching the jax boundary) and the k-th largest magnitude via
//        4x8-bit radix select, then publishes d_thr[b] + d_flag[b].
//  O(b): spin (volatile poll + nanosleep) on d_flag[b], then emit output:
//        kept rows copy W (mostly L2 hits thanks to the interleave), dropped
//        rows write zeros.
//  Liveness: N-blocks never wait; every O(b) group is scheduled after N(b)'s
//  group, and N-blocks always retire => flags always eventually set.
// ---------------------------------------------------------------------------
__global__ void __launch_bounds__(256)
fused_all_kernel(const float4* __restrict__ w, float4* __restrict__ out,
                 const float* __restrict__ logits,
                 const float* __restrict__ score_w,
                 const float* __restrict__ score_b) {
    const int tid  = threadIdx.x;
    const int lane = tid & 31;
    const int warp = tid >> 5;

    const int gid = blockIdx.x >> 9;          // group 0..15
    const int sub = blockIdx.x & 511;         // block within group
    const int b   = g_batch[gid];

    if (g_phase[gid] == 0) {
        // =================== Phase N: norms (+ threshold) ===================
        const int gwarp = b * RR + (sub << 3) + warp;     // 8 rows per block

        __shared__ double   sdot[256];
        __shared__ unsigned hist[256], sufA[256], sufB[256];
        __shared__ unsigned sh_prefix, sh_done;
        __shared__ int      sh_k;

        {
            const float4* row = w + (size_t)gwarp * 256;
            float s0 = 0.f, c0 = 0.f, s1 = 0.f, c1 = 0.f;
            float s2 = 0.f, c2 = 0.f, s3 = 0.f, c3 = 0.f;
#pragma unroll
            for (int i = 0; i < 8; i++) {
                float4 v = row[lane + i * 32];
                twosum_acc(s0, c0, v.x * v.x);
                twosum_acc(s1, c1, v.y * v.y);
                twosum_acc(s2, c2, v.z * v.z);
                twosum_acc(s3, c3, v.w * v.w);
            }
            twosum_merge(s0, c0, s1, c1);
            twosum_merge(s2, c2, s3, c3);
            twosum_merge(s0, c0, s2, c2);
#pragma unroll
            for (int off = 16; off > 0; off >>= 1) {
                float so = __shfl_down_sync(0xffffffffu, s0, off);
                float co = __shfl_down_sync(0xffffffffu, c0, off);
                twosum_merge(s0, c0, so, co);
            }
            if (lane == 0) d_mags[gwarp] = sqrtf(s0 + c0);
        }

        __syncthreads();                                  // all 8 d_mags written
        if (tid == 0) {
            __threadfence();                              // publish d_mags
            sh_done = atomicAdd(&d_cnt[b], 1u);
        }
        __syncthreads();
        if (sh_done != 511u) return;                      // not the last block

        // ---- (a) fp64 score dot -> fp32 sigmoid -> k ----
        double acc = 0.0;
        for (int j = tid; j < CC; j += 256)
            acc += (double)logits[b * CC + j] * (double)score_w[j];
        sdot[tid] = acc;
        __syncthreads();
#pragma unroll
        for (int st = 128; st > 0; st >>= 1) {
            if (tid < st) sdot[tid] += sdot[tid + st];
            __syncthreads();
        }
        if (tid == 0) {
            float s = (float)sdot[0] + score_b[0];
            float kf = 1.0f / (1.0f + expf(-s));          // fp32 sigmoid, like ref
            int k = (int)(kf * (float)RR);                 // fp32 mul + trunc, like ref
            if (k < 1) k = 1;
            if (k > RR) k = RR;
            sh_k = k;
            d_cnt[b] = 0;                                 // reset for replay
        }
        __syncthreads();

        // ---- (b) radix select k-th largest among d_mags[b*RR .. +RR) ----
        unsigned prefix = 0;
        int k = sh_k;
        const float* mags = d_mags + b * RR;

        for (int shift = 24; shift >= 0; shift -= 8) {
            hist[tid] = 0;
            __syncthreads();
            unsigned hi_mask = (shift == 24) ? 0u : (0xFFFFFFFFu << (shift + 8));
#pragma unroll
            for (int i = 0; i < RR / 256; i++) {          // 16 values per thread
                unsigned key = __float_as_uint(__ldcg(&mags[tid + i * 256]));
                unsigned digit = ((key & hi_mask) == (prefix & hi_mask))
                                     ? ((key >> shift) & 0xFFu) : 256u;
                unsigned peers = __match_any_sync(0xffffffffu, digit);
                int leader = __ffs(peers) - 1;
                if (lane == leader && digit < 256u)
                    atomicAdd(&hist[digit], (unsigned)__popc(peers));
            }
            __syncthreads();

            sufA[tid] = hist[tid];                        // suffix sum over bins
            __syncthreads();
            unsigned* src = sufA;
            unsigned* dst = sufB;
#pragma unroll
            for (int off = 1; off < 256; off <<= 1) {
                unsigned add = (tid + off < 256) ? src[tid + off] : 0u;
                dst[tid] = src[tid] + add;
                __syncthreads();
                unsigned* t = src; src = dst; dst = t;
            }
            unsigned mycum  = src[tid];
            unsigned nextcum = (tid == 255) ? 0u : src[tid + 1];
            if (mycum >= (unsigned)k && nextcum < (unsigned)k) {
                sh_prefix = prefix | ((unsigned)tid << shift);
                sh_k = k - (int)nextcum;
            }
            __syncthreads();
            prefix = sh_prefix;
            k = sh_k;
            __syncthreads();
        }

        if (tid == 0) {
            d_thr[b] = __uint_as_float(prefix);
            __threadfence();                              // release
            atomicExch(&d_flag[b], 1u);                   // thr ready
        }
    } else {
        // ======================= Phase O: output ===========================
        const int gwarp = b * RR + (sub << 3) + warp;     // same row mapping

        __shared__ float sh_thr;

        if (tid == 0) {
            // Volatile poll (plain L2 read), not an atomic RMW: spinning
            // blocks must not serialize on the LTS atomic unit while the
            // N groups are streaming.
            while (*(volatile unsigned*)&d_flag[b] == 0u)
                __nanosleep(128);
            __threadfence();                              // acquire: order reads
            sh_thr = __ldcg(&d_thr[b]);
        }
        __syncthreads();
        const float thr = sh_thr;

        float4* orow = out + (size_t)gwarp * 256;
        if (__ldcg(&d_mags[gwarp]) >= thr) {
            const float4* row = w + (size_t)gwarp * 256;
#pragma unroll
            for (int i = 0; i < 8; i++)
                orow[lane + i * 32] = row[lane + i * 32]; // kept: copy (L2 hits)
        } else {
            const float4 z = make_float4(0.f, 0.f, 0.f, 0.f);
#pragma unroll
            for (int i = 0; i < 8; i++)
                orow[lane + i * 32] = z;                  // dropped: zeros
        }

        __syncthreads();
        if (tid == 0) {                                   // last out block resets
            unsigned old = atomicAdd(&d_ocnt[b], 1u);
            if (old == 511u) {
                d_ocnt[b] = 0;
                atomicExch(&d_flag[b], 0u);               // reset for replay
            }
        }
    }
}

// ---------------------------------------------------------------------------
extern "C" void kernel_launch(void* const* d_in, const int* in_sizes, int n_in,
                              void* d_out, int out_size) {
    const float* w       = (const float*)d_in[0];  // [8,4096,1024] f32
    const float* logits  = (const float*)d_in[1];  // [8,1024] f32
    const float* score_w = (const float*)d_in[2];  // [1024,1] f32
    const float* score_b = (const float*)d_in[3];  // [1] f32

    (void)in_sizes; (void)n_in; (void)out_size;

    fused_all_kernel<<<16 * 512, 256>>>(
        (const float4*)w, (float4*)d_out, logits, score_w, score_b);
}

// round 16
// speedup vs baseline: 1.4451x; 1.4451x over previous
#include <cuda_runtime.h>
#include <math.h>

#define BB 8
#define RR 4096
#define CC 1024
#define NROW (BB * RR)
#define C_BLKS 4096       // bids [0,4096): copy + norms (+ last-block select)
#define Z_BLKS 4096       // bids [4096,8192): zero dropped rows (scheduled LAST)

// Scratch + sync state (no allocations; zero-init at load, self-reset per run).
__device__ float    d_mags[NROW];
__device__ float    d_thr[BB];
__device__ unsigned d_cnt[BB];    // C-blocks-done counter per batch
__device__ unsigned d_flag[BB];   // thr-ready flag per batch
__device__ unsigned d_ocnt[BB];   // Z-blocks-done counter per batch (reset)

// Branch-free two-sum accumulate: s += t with running compensation c.
__device__ __forceinline__ void twosum_acc(float& s, float& c, float t) {
    float y  = s + t;
    float bp = y - s;
    c += (s - (y - bp)) + (t - bp);
    s = y;
}
__device__ __forceinline__ void twosum_merge(float& s, float& c, float so, float co) {
    float S  = s + so;
    float bp = S - s;
    float e  = (s - (S - bp)) + (so - bp);
    c = c + co + e;
    s = S;
}

// ---------------------------------------------------------------------------
// One launch, two phases, ALL C-blocks scheduled before ALL Z-blocks (spin
// blocks only ever at the end of the grid — the R15 interleave regression
// showed early-resident spinners starve the streaming phase).
//
//  C (bids 0..4095): copy W -> out + compensated-fp32 per-row L2 norms
//    (error ~2^-45 << ~1.4e-5 order-statistic gap -> top-k boundary matches
//    the jax fp32 reference). Last block per batch (atomic counter):
//      - fp64 score dot -> fp32 sigmoid -> trunc -> k  (jax-exact boundary)
//      - stages the 4096 mags into SMEM ONCE, then 4x8-bit radix select
//        against smem (fast: no repeated L2 round-trips), publishes thr+flag.
//  Z (bids 4096..8191): spin (volatile poll + nanosleep) on flag, then zero
//    the dropped rows (kept rows already final from the C-phase copy).
// ---------------------------------------------------------------------------
__global__ void __launch_bounds__(256)
fused_all_kernel(const float4* __restrict__ w, float4* __restrict__ out,
                 const float* __restrict__ logits,
                 const float* __restrict__ score_w,
                 const float* __restrict__ score_b) {
    const int tid  = threadIdx.x;
    const int lane = tid & 31;
    const int warp = tid >> 5;

    if (blockIdx.x < C_BLKS) {
        // ================= Phase C: copy + norms (+ select) =================
        const int gwarp = (blockIdx.x << 3) + warp;       // 8 rows per block
        const int b = blockIdx.x >> 9;                    // 512 blocks per batch

        __shared__ unsigned skeys[RR];                    // 16KB: staged mags
        __shared__ double   sdot[256];
        __shared__ unsigned hist[256], sufA[256], sufB[256];
        __shared__ unsigned sh_prefix, sh_done;
        __shared__ int      sh_k;

        {
            const float4* row = w + (size_t)gwarp * 256;
            float4* orow = out + (size_t)gwarp * 256;
            float s0 = 0.f, c0 = 0.f, s1 = 0.f, c1 = 0.f;
            float s2 = 0.f, c2 = 0.f, s3 = 0.f, c3 = 0.f;
#pragma unroll
            for (int i = 0; i < 8; i++) {
                float4 v = row[lane + i * 32];
                orow[lane + i * 32] = v;                  // streaming copy
                twosum_acc(s0, c0, v.x * v.x);
                twosum_acc(s1, c1, v.y * v.y);
                twosum_acc(s2, c2, v.z * v.z);
                twosum_acc(s3, c3, v.w * v.w);
            }
            twosum_merge(s0, c0, s1, c1);
            twosum_merge(s2, c2, s3, c3);
            twosum_merge(s0, c0, s2, c2);
#pragma unroll
            for (int off = 16; off > 0; off >>= 1) {
                float so = __shfl_down_sync(0xffffffffu, s0, off);
                float co = __shfl_down_sync(0xffffffffu, c0, off);
                twosum_merge(s0, c0, so, co);
            }
            if (lane == 0) d_mags[gwarp] = sqrtf(s0 + c0);
        }

        __syncthreads();                                  // all 8 d_mags written
        if (tid == 0) {
            __threadfence();                              // publish d_mags
            sh_done = atomicAdd(&d_cnt[b], 1u);
        }
        __syncthreads();
        if (sh_done != 511u) return;                      // not the last block

        // ---- stage this batch's 4096 mags into smem (ONE L2 round) ----
        {
            const float* mags = d_mags + b * RR;
#pragma unroll
            for (int i = 0; i < RR / 256; i++)
                skeys[tid + i * 256] = __float_as_uint(__ldcg(&mags[tid + i * 256]));
        }

        // ---- (a) fp64 score dot -> fp32 sigmoid -> k ----
        double acc = 0.0;
        for (int j = tid; j < CC; j += 256)
            acc += (double)logits[b * CC + j] * (double)score_w[j];
        sdot[tid] = acc;
        __syncthreads();
#pragma unroll
        for (int st = 128; st > 0; st >>= 1) {
            if (tid < st) sdot[tid] += sdot[tid + st];
            __syncthreads();
        }
        if (tid == 0) {
            float s = (float)sdot[0] + score_b[0];
            float kf = 1.0f / (1.0f + expf(-s));          // fp32 sigmoid, like ref
            int k = (int)(kf * (float)RR);                 // fp32 mul + trunc, like ref
            if (k < 1) k = 1;
            if (k > RR) k = RR;
            sh_k = k;
            d_cnt[b] = 0;                                 // reset for replay
        }
        __syncthreads();

        // ---- (b) radix select k-th largest, keys in SMEM ----
        unsigned prefix = 0;
        int k = sh_k;
        for (int shift = 24; shift >= 0; shift -= 8) {
            hist[tid] = 0;
            __syncthreads();
            unsigned hi_mask = (shift == 24) ? 0u : (0xFFFFFFFFu << (shift + 8));
#pragma unroll
            for (int i = 0; i < RR / 256; i++) {          // 16 keys per thread
                unsigned key = skeys[tid + i * 256];      // conflict-free stride
                unsigned digit = ((key & hi_mask) == (prefix & hi_mask))
                                     ? ((key >> shift) & 0xFFu) : 256u;
                unsigned peers = __match_any_sync(0xffffffffu, digit);
                int leader = __ffs(peers) - 1;
                if (lane == leader && digit < 256u)
                    atomicAdd(&hist[digit], (unsigned)__popc(peers));
            }
            __syncthreads();

            sufA[tid] = hist[tid];                        // suffix sum over bins
            __syncthreads();
            unsigned* src = sufA;
            unsigned* dst = sufB;
#pragma unroll
            for (int off = 1; off < 256; off <<= 1) {
                unsigned add = (tid + off < 256) ? src[tid + off] : 0u;
                dst[tid] = src[tid] + add;
                __syncthreads();
                unsigned* t = src; src = dst; dst = t;
            }
            unsigned mycum  = src[tid];
            unsigned nextcum = (tid == 255) ? 0u : src[tid + 1];
            if (mycum >= (unsigned)k && nextcum < (unsigned)k) {
                sh_prefix = prefix | ((unsigned)tid << shift);
                sh_k = k - (int)nextcum;
            }
            __syncthreads();
            prefix = sh_prefix;
            k = sh_k;
            __syncthreads();
        }

        if (tid == 0) {
            d_thr[b] = __uint_as_float(prefix);
            __threadfence();                              // release
            atomicExch(&d_flag[b], 1u);                   // thr ready
        }
    } else {
        // ================= Phase Z: zero dropped rows =======================
        const int obid = blockIdx.x - C_BLKS;
        const int gwarp = (obid << 3) + warp;             // same row mapping
        const int b = obid >> 9;

        __shared__ float sh_thr;

        if (tid == 0) {
            // Volatile poll (plain L2 read): spinning blocks must not
            // serialize on the LTS atomic unit while C-phase streams.
            while (*(volatile unsigned*)&d_flag[b] == 0u)
                __nanosleep(128);
            __threadfence();                              // acquire
            sh_thr = __ldcg(&d_thr[b]);
        }
        __syncthreads();
        const float thr = sh_thr;

        const bool drop = __ldcg(&d_mags[gwarp]) < thr;
        if (drop) {
            float4* orow = out + (size_t)gwarp * 256;
            const float4 z = make_float4(0.f, 0.f, 0.f, 0.f);
#pragma unroll
            for (int i = 0; i < 8; i++)
                orow[lane + i * 32] = z;                  // dropped: zeros
        }

        __syncthreads();
        if (tid == 0) {                                   // last Z block resets
            unsigned old = atomicAdd(&d_ocnt[b], 1u);
            if (old == 511u) {
                d_ocnt[b] = 0;
                atomicExch(&d_flag[b], 0u);               // reset for replay
            }
        }
    }
}

// ---------------------------------------------------------------------------
extern "C" void kernel_launch(void* const* d_in, const int* in_sizes, int n_in,
                              void* d_out, int out_size) {
    const float* w       = (const float*)d_in[0];  // [8,4096,1024] f32
    const float* logits  = (const float*)d_in[1];  // [8,1024] f32
    const float* score_w = (const float*)d_in[2];  // [1024,1] f32
    const float* score_b = (const float*)d_in[3];  // [1] f32

    (void)in_sizes; (void)n_in; (void)out_size;

    fused_all_kernel<<<C_BLKS + Z_BLKS, 256>>>(
        (const float4*)w, (float4*)d_out, logits, score_w, score_b);
}